// round 7
// baseline (speedup 1.0000x reference)
#include <cuda_runtime.h>
#include <math.h>

#define BQ 2048
#define NQ 128
#define HQ 512
#define TAUC 0.05f
#define BT 8
#define NITER 10   // Richardson iterations (even)

// scratch (allocation-free rule: __device__ globals)
__device__ float g_q[BQ * NQ];
__device__ float g_p[BQ * NQ];
__device__ float g_o[BQ * NQ];

// ---------------------------------------------------------------------------
// Kernel A: one weight matrix per CTA (blockIdx.y selects Wq/Wp/Wo).
// grid = (BQ/BT, 3). 256 threads: n = tid&127, half = tid>>7, 4 batches each.
// ---------------------------------------------------------------------------
__global__ void __launch_bounds__(256) gemm_act_kernel(
    const float* __restrict__ hidden,
    const float* __restrict__ Wq, const float* __restrict__ Wp,
    const float* __restrict__ Wo,
    const float* __restrict__ bq, const float* __restrict__ bp,
    const float* __restrict__ bo)
{
    __shared__ float4 Ht[BT * HQ / 4];   // 8x512 floats = 16 KB
    const int tid = threadIdx.x;
    const int b0 = blockIdx.x * BT;
    const int w  = blockIdx.y;

    const float* W    = (w == 0) ? Wq : (w == 1) ? Wp : Wo;
    const float* bias = (w == 0) ? bq : (w == 1) ? bp : bo;
    float* gout       = (w == 0) ? g_q : (w == 1) ? g_p : g_o;

    const float4* hg = (const float4*)(hidden + (size_t)b0 * HQ);
#pragma unroll
    for (int i = 0; i < (BT * HQ / 4) / 256; i++)
        Ht[tid + 256 * i] = hg[tid + 256 * i];
    __syncthreads();

    const int n = tid & 127;
    const int half = tid >> 7;

    const float4* w4 = (const float4*)(W + (size_t)n * HQ);
    const float4* h0 = &Ht[(half * 4 + 0) * (HQ / 4)];
    const float4* h1 = &Ht[(half * 4 + 1) * (HQ / 4)];
    const float4* h2 = &Ht[(half * 4 + 2) * (HQ / 4)];
    const float4* h3 = &Ht[(half * 4 + 3) * (HQ / 4)];

    float acc[4] = {0.f, 0.f, 0.f, 0.f};

#pragma unroll 8
    for (int k4 = 0; k4 < HQ / 4; k4++) {
        const float4 wv = w4[k4];
        float4 h;
        h = h0[k4];
        acc[0] = fmaf(h.x, wv.x, fmaf(h.y, wv.y, fmaf(h.z, wv.z, fmaf(h.w, wv.w, acc[0]))));
        h = h1[k4];
        acc[1] = fmaf(h.x, wv.x, fmaf(h.y, wv.y, fmaf(h.z, wv.z, fmaf(h.w, wv.w, acc[1]))));
        h = h2[k4];
        acc[2] = fmaf(h.x, wv.x, fmaf(h.y, wv.y, fmaf(h.z, wv.z, fmaf(h.w, wv.w, acc[2]))));
        h = h3[k4];
        acc[3] = fmaf(h.x, wv.x, fmaf(h.y, wv.y, fmaf(h.z, wv.z, fmaf(h.w, wv.w, acc[3]))));
    }

    const float bv = bias[n];
#pragma unroll
    for (int m = 0; m < 4; m++) {
        const int b = b0 + half * 4 + m;
        const float l = acc[m] + bv;
        float v;
        if (w == 0) {
            v = tanhf(l);                                         // q
        } else if (w == 1) {
            v = 1.0f / (1.0f + expf(-l));                         // p
        } else {
            v = fmaxf(l, 0.0f) + log1pf(expf(-fabsf(l))) + 1e-6f; // omega
        }
        gout[b * NQ + n] = v;
    }
}

// ---------------------------------------------------------------------------
// Kernel B: per-batch solve of (I + M D) mu = pi + M t via Richardson.
// 512 threads per batch: thread (r = tid>>2, h = tid&3) owns E[r][h*32..+31]
// in registers. x broadcast from smem; 2-level shfl reduce over h.
// ---------------------------------------------------------------------------
__device__ __forceinline__ float matvec_quarter(const float* __restrict__ E,
                                                const float* __restrict__ xbase,
                                                int h)
{
    const float4* x4 = (const float4*)xbase + h * 8;
    float a0 = 0.f, a1 = 0.f, a2 = 0.f, a3 = 0.f;
#pragma unroll
    for (int k = 0; k < 8; k++) {
        const float4 xv = x4[k];
        a0 = fmaf(E[4 * k + 0], xv.x, a0);
        a1 = fmaf(E[4 * k + 1], xv.y, a1);
        a2 = fmaf(E[4 * k + 2], xv.z, a2);
        a3 = fmaf(E[4 * k + 3], xv.w, a3);
    }
    float sum = (a0 + a1) + (a2 + a3);
    sum += __shfl_xor_sync(0xffffffffu, sum, 1);
    sum += __shfl_xor_sync(0xffffffffu, sum, 2);
    return sum;
}

__global__ void __launch_bounds__(512) solve_kernel(
    const float* __restrict__ pi,
    const float* __restrict__ sigma,
    float* __restrict__ out)
{
    __shared__ __align__(16) float sm_d[NQ];
    __shared__ __align__(16) float sm_u[NQ];
    __shared__ __align__(16) float sm_a[NQ];
    __shared__ __align__(16) float xA[NQ];
    __shared__ __align__(16) float xB[NQ];

    const int tid = threadIdx.x;
    const int b = blockIdx.x;
    const int r = tid >> 2;
    const int h = tid & 3;

    if (tid < NQ) {
        const float q  = g_q[b * NQ + tid];
        const float p  = g_p[b * NQ + tid];
        const float om = g_o[b * NQ + tid];
        const float d  = p * p / om + 1e-6f;
        sm_d[tid] = d;
        sm_u[tid] = (p * q / om) / d;
        sm_a[tid] = pi[b * NQ + tid];
    }
    __syncthreads();

    // Build E = (TAU*sigma + 1e-6 I) * diag(d) into registers (32 per thread).
    float E[32];
    const float4* sg = (const float4*)(sigma + (size_t)b * NQ * NQ) + r * 32 + h * 8;
    const float4* d4 = (const float4*)sm_d + h * 8;
#pragma unroll
    for (int k = 0; k < 8; k++) {
        const float4 s = sg[k];
        const float4 dv = d4[k];
        const int j = h * 32 + 4 * k;
        E[4 * k + 0] = (TAUC * s.x + ((r == j + 0) ? 1e-6f : 0.f)) * dv.x;
        E[4 * k + 1] = (TAUC * s.y + ((r == j + 1) ? 1e-6f : 0.f)) * dv.y;
        E[4 * k + 2] = (TAUC * s.z + ((r == j + 2) ? 1e-6f : 0.f)) * dv.z;
        E[4 * k + 3] = (TAUC * s.w + ((r == j + 3) ? 1e-6f : 0.f)) * dv.w;
    }

    // a = pi + M t = pi + E * (t./d);  x0 = a
    {
        const float s = matvec_quarter(E, sm_u, h);
        if (h == 0) {
            const float a = sm_a[r] + s;
            sm_a[r] = a;
            xA[r] = a;
        }
    }
    __syncthreads();

    // Richardson: x <- a - E x   (converges to (I + E)^{-1} a)
#pragma unroll 1
    for (int it = 0; it < NITER / 2; it++) {
        float s = matvec_quarter(E, xA, h);
        if (h == 0) xB[r] = sm_a[r] - s;
        __syncthreads();
        s = matvec_quarter(E, xB, h);
        if (h == 0) xA[r] = sm_a[r] - s;
        __syncthreads();
    }

    if (tid < NQ) out[b * NQ + tid] = xA[tid];
}

// ---------------------------------------------------------------------------
extern "C" void kernel_launch(void* const* d_in, const int* in_sizes, int n_in,
                              void* d_out, int out_size)
{
    const float* hidden = (const float*)d_in[0];
    const float* pi     = (const float*)d_in[1];
    const float* sigma  = (const float*)d_in[2];
    const float* Wq     = (const float*)d_in[3];
    const float* bq     = (const float*)d_in[4];
    const float* Wp     = (const float*)d_in[5];
    const float* bp     = (const float*)d_in[6];
    const float* Wo     = (const float*)d_in[7];
    const float* bo     = (const float*)d_in[8];

    dim3 gridA(BQ / BT, 3, 1);
    gemm_act_kernel<<<gridA, 256>>>(hidden, Wq, Wp, Wo, bq, bp, bo);
    solve_kernel<<<BQ, 512>>>(pi, sigma, (float*)d_out);
}

// round 8
// speedup vs baseline: 1.0032x; 1.0032x over previous
#include <cuda_runtime.h>
#include <math.h>

#define BQ 2048
#define NQ 128
#define HQ 512
#define TAUC 0.05f
#define BT 8
#define NITER 10   // Richardson iterations (even)

// scratch (allocation-free rule: __device__ globals)
__device__ float g_q[BQ * NQ];
__device__ float g_p[BQ * NQ];
__device__ float g_o[BQ * NQ];

// ---------------------------------------------------------------------------
// Kernel A: one weight matrix per CTA (blockIdx.y selects Wq/Wp/Wo).
// grid = (BQ/BT, 3). 256 threads: n = tid&127, half = tid>>7, 4 batches each.
// ---------------------------------------------------------------------------
__global__ void __launch_bounds__(256) gemm_act_kernel(
    const float* __restrict__ hidden,
    const float* __restrict__ Wq, const float* __restrict__ Wp,
    const float* __restrict__ Wo,
    const float* __restrict__ bq, const float* __restrict__ bp,
    const float* __restrict__ bo)
{
    __shared__ float4 Ht[BT * HQ / 4];   // 8x512 floats = 16 KB
    const int tid = threadIdx.x;
    const int b0 = blockIdx.x * BT;
    const int w  = blockIdx.y;

    const float* W    = (w == 0) ? Wq : (w == 1) ? Wp : Wo;
    const float* bias = (w == 0) ? bq : (w == 1) ? bp : bo;
    float* gout       = (w == 0) ? g_q : (w == 1) ? g_p : g_o;

    const float4* hg = (const float4*)(hidden + (size_t)b0 * HQ);
#pragma unroll
    for (int i = 0; i < (BT * HQ / 4) / 256; i++)
        Ht[tid + 256 * i] = hg[tid + 256 * i];
    __syncthreads();

    const int n = tid & 127;
    const int half = tid >> 7;

    const float4* w4 = (const float4*)(W + (size_t)n * HQ);
    const float4* h0 = &Ht[(half * 4 + 0) * (HQ / 4)];
    const float4* h1 = &Ht[(half * 4 + 1) * (HQ / 4)];
    const float4* h2 = &Ht[(half * 4 + 2) * (HQ / 4)];
    const float4* h3 = &Ht[(half * 4 + 3) * (HQ / 4)];

    float acc[4] = {0.f, 0.f, 0.f, 0.f};

#pragma unroll 8
    for (int k4 = 0; k4 < HQ / 4; k4++) {
        const float4 wv = w4[k4];
        float4 h;
        h = h0[k4];
        acc[0] = fmaf(h.x, wv.x, fmaf(h.y, wv.y, fmaf(h.z, wv.z, fmaf(h.w, wv.w, acc[0]))));
        h = h1[k4];
        acc[1] = fmaf(h.x, wv.x, fmaf(h.y, wv.y, fmaf(h.z, wv.z, fmaf(h.w, wv.w, acc[1]))));
        h = h2[k4];
        acc[2] = fmaf(h.x, wv.x, fmaf(h.y, wv.y, fmaf(h.z, wv.z, fmaf(h.w, wv.w, acc[2]))));
        h = h3[k4];
        acc[3] = fmaf(h.x, wv.x, fmaf(h.y, wv.y, fmaf(h.z, wv.z, fmaf(h.w, wv.w, acc[3]))));
    }

    const float bv = bias[n];
#pragma unroll
    for (int m = 0; m < 4; m++) {
        const int b = b0 + half * 4 + m;
        const float l = acc[m] + bv;
        float v;
        if (w == 0) {
            v = tanhf(l);                                         // q
        } else if (w == 1) {
            v = 1.0f / (1.0f + expf(-l));                         // p
        } else {
            v = fmaxf(l, 0.0f) + log1pf(expf(-fabsf(l))) + 1e-6f; // omega
        }
        gout[b * NQ + n] = v;
    }
}

// ---------------------------------------------------------------------------
// Kernel B: per-batch solve of (I + M D) mu = pi + M t via Richardson.
// 512 threads per batch: thread (r = tid>>2, h = tid&3) owns E[r][h*32..+31]
// in registers. x broadcast from smem; 2-level shfl reduce over h.
// ---------------------------------------------------------------------------
__device__ __forceinline__ float matvec_quarter(const float* __restrict__ E,
                                                const float* __restrict__ xbase,
                                                int h)
{
    const float4* x4 = (const float4*)xbase + h * 8;
    float a0 = 0.f, a1 = 0.f, a2 = 0.f, a3 = 0.f;
#pragma unroll
    for (int k = 0; k < 8; k++) {
        const float4 xv = x4[k];
        a0 = fmaf(E[4 * k + 0], xv.x, a0);
        a1 = fmaf(E[4 * k + 1], xv.y, a1);
        a2 = fmaf(E[4 * k + 2], xv.z, a2);
        a3 = fmaf(E[4 * k + 3], xv.w, a3);
    }
    float sum = (a0 + a1) + (a2 + a3);
    sum += __shfl_xor_sync(0xffffffffu, sum, 1);
    sum += __shfl_xor_sync(0xffffffffu, sum, 2);
    return sum;
}

__global__ void __launch_bounds__(512) solve_kernel(
    const float* __restrict__ pi,
    const float* __restrict__ sigma,
    float* __restrict__ out)
{
    __shared__ __align__(16) float sm_d[NQ];
    __shared__ __align__(16) float sm_u[NQ];
    __shared__ __align__(16) float sm_a[NQ];
    __shared__ __align__(16) float xA[NQ];
    __shared__ __align__(16) float xB[NQ];

    const int tid = threadIdx.x;
    const int b = blockIdx.x;
    const int r = tid >> 2;
    const int h = tid & 3;

    if (tid < NQ) {
        const float q  = g_q[b * NQ + tid];
        const float p  = g_p[b * NQ + tid];
        const float om = g_o[b * NQ + tid];
        const float d  = p * p / om + 1e-6f;
        sm_d[tid] = d;
        sm_u[tid] = (p * q / om) / d;
        sm_a[tid] = pi[b * NQ + tid];
    }
    __syncthreads();

    // Build E = (TAU*sigma + 1e-6 I) * diag(d) into registers (32 per thread).
    float E[32];
    const float4* sg = (const float4*)(sigma + (size_t)b * NQ * NQ) + r * 32 + h * 8;
    const float4* d4 = (const float4*)sm_d + h * 8;
#pragma unroll
    for (int k = 0; k < 8; k++) {
        const float4 s = sg[k];
        const float4 dv = d4[k];
        const int j = h * 32 + 4 * k;
        E[4 * k + 0] = (TAUC * s.x + ((r == j + 0) ? 1e-6f : 0.f)) * dv.x;
        E[4 * k + 1] = (TAUC * s.y + ((r == j + 1) ? 1e-6f : 0.f)) * dv.y;
        E[4 * k + 2] = (TAUC * s.z + ((r == j + 2) ? 1e-6f : 0.f)) * dv.z;
        E[4 * k + 3] = (TAUC * s.w + ((r == j + 3) ? 1e-6f : 0.f)) * dv.w;
    }

    // a = pi + M t = pi + E * (t./d);  x0 = a
    {
        const float s = matvec_quarter(E, sm_u, h);
        if (h == 0) {
            const float a = sm_a[r] + s;
            sm_a[r] = a;
            xA[r] = a;
        }
    }
    __syncthreads();

    // Richardson: x <- a - E x   (converges to (I + E)^{-1} a)
#pragma unroll 1
    for (int it = 0; it < NITER / 2; it++) {
        float s = matvec_quarter(E, xA, h);
        if (h == 0) xB[r] = sm_a[r] - s;
        __syncthreads();
        s = matvec_quarter(E, xB, h);
        if (h == 0) xA[r] = sm_a[r] - s;
        __syncthreads();
    }

    if (tid < NQ) out[b * NQ + tid] = xA[tid];
}

// ---------------------------------------------------------------------------
extern "C" void kernel_launch(void* const* d_in, const int* in_sizes, int n_in,
                              void* d_out, int out_size)
{
    const float* hidden = (const float*)d_in[0];
    const float* pi     = (const float*)d_in[1];
    const float* sigma  = (const float*)d_in[2];
    const float* Wq     = (const float*)d_in[3];
    const float* bq     = (const float*)d_in[4];
    const float* Wp     = (const float*)d_in[5];
    const float* bp     = (const float*)d_in[6];
    const float* Wo     = (const float*)d_in[7];
    const float* bo     = (const float*)d_in[8];

    dim3 gridA(BQ / BT, 3, 1);
    gemm_act_kernel<<<gridA, 256>>>(hidden, Wq, Wp, Wo, bq, bp, bo);
    solve_kernel<<<BQ, 512>>>(pi, sigma, (float*)d_out);
}

// round 11
// speedup vs baseline: 2.5163x; 2.5081x over previous
#include <cuda_runtime.h>
#include <math.h>

#define BQ 2048
#define NQ 128
#define HQ 512
#define TAUC 0.05f
#define BT 8
#define KC 32
#define NITER 6    // Richardson iterations (even); fp32 floor reached by ~8 apps

// padded index: 32-float groups padded to 36 words -> banks (4g + i) % 32
#define PX(i) ((((i) >> 5) * 36) + ((i) & 31))

// scratch (allocation-free rule: __device__ globals)
__device__ float g_q[BQ * NQ];
__device__ float g_p[BQ * NQ];
__device__ float g_o[BQ * NQ];

// ---------------------------------------------------------------------------
// Kernel A: tiled GEMM. CTA = 8 batches x 128 n, one weight (blockIdx.y).
// W staged through smem (coalesced LDG, pad-33 conflict-free LDS).
// 256 threads: n = tid&127, kh = tid>>7 splits the k-range; reduce at end.
// Smem: 16 KB (Ht) + 16.5 KB (Wt) = 32.5 KB < 48 KB static limit.
// ---------------------------------------------------------------------------
__global__ void __launch_bounds__(256) gemm_act_kernel(
    const float* __restrict__ hidden,
    const float* __restrict__ Wq, const float* __restrict__ Wp,
    const float* __restrict__ Wo,
    const float* __restrict__ bq, const float* __restrict__ bp,
    const float* __restrict__ bo)
{
    __shared__ float Ht[BT][HQ];        // 16 KB
    __shared__ float Wt[NQ][KC + 1];    // 16.5 KB, pad 33 -> bank (n+kk)%32

    const int tid = threadIdx.x;
    const int b0 = blockIdx.x * BT;
    const int w  = blockIdx.y;

    const float* W    = (w == 0) ? Wq : (w == 1) ? Wp : Wo;
    const float* bias = (w == 0) ? bq : (w == 1) ? bp : bo;
    float* gout       = (w == 0) ? g_q : (w == 1) ? g_p : g_o;

    // load hidden tile (coalesced float4)
    {
        const float4* hg = (const float4*)(hidden + (size_t)b0 * HQ);
        float4* hs = (float4*)&Ht[0][0];
#pragma unroll
        for (int i = 0; i < (BT * HQ / 4) / 256; i++)
            hs[tid + 256 * i] = hg[tid + 256 * i];
    }

    const int n    = tid & 127;
    const int kh   = tid >> 7;
    const int wrp  = tid >> 5;
    const int lane = tid & 31;
    const int rowsub = lane >> 3;      // 4 rows per warp per instr
    const int f4     = lane & 7;       // 8 float4 per 128B row
    const float4* W4 = (const float4*)W;

    float acc[8] = {0.f, 0.f, 0.f, 0.f, 0.f, 0.f, 0.f, 0.f};

#pragma unroll 1
    for (int c = 0; c < HQ / KC; c++) {
        __syncthreads();
        // stage W[:, c*32 .. +31]: each warp 4 rows/instr, 4 instrs = 16 rows
#pragma unroll
        for (int i = 0; i < 4; i++) {
            const int row = wrp * 16 + i * 4 + rowsub;
            const float4 v = W4[(size_t)row * (HQ / 4) + c * (KC / 4) + f4];
            Wt[row][f4 * 4 + 0] = v.x;
            Wt[row][f4 * 4 + 1] = v.y;
            Wt[row][f4 * 4 + 2] = v.z;
            Wt[row][f4 * 4 + 3] = v.w;
        }
        __syncthreads();

        const int k0 = c * KC;
#pragma unroll
        for (int j = 0; j < 4; j++) {
            const int kk = kh * 16 + j * 4;
            const float w0 = Wt[n][kk + 0];
            const float w1 = Wt[n][kk + 1];
            const float w2 = Wt[n][kk + 2];
            const float w3 = Wt[n][kk + 3];
#pragma unroll
            for (int m = 0; m < 8; m++) {
                const float4 hv = *(const float4*)&Ht[m][k0 + kk];
                acc[m] = fmaf(hv.x, w0, fmaf(hv.y, w1,
                         fmaf(hv.z, w2, fmaf(hv.w, w3, acc[m]))));
            }
        }
    }

    // combine the two k-halves via smem (reuse Wt as scratch: 1024 floats)
    __syncthreads();
    float* red = &Wt[0][0];
    if (kh == 1) {
#pragma unroll
        for (int m = 0; m < 8; m++) red[n * 8 + m] = acc[m];
    }
    __syncthreads();
    if (kh == 0) {
        const float bv = bias[n];
#pragma unroll
        for (int m = 0; m < 8; m++) {
            const float l = acc[m] + red[n * 8 + m] + bv;
            float v;
            if (w == 0) {
                v = tanhf(l);                                         // q
            } else if (w == 1) {
                v = 1.0f / (1.0f + expf(-l));                         // p
            } else {
                v = fmaxf(l, 0.0f) + log1pf(expf(-fabsf(l))) + 1e-6f; // omega
            }
            gout[(size_t)(b0 + m) * NQ + n] = v;
        }
    }
}

// ---------------------------------------------------------------------------
// Kernel B: per-batch solve of (I + M D) mu = pi + M t via Richardson.
// 512 threads: thread (r = tid>>2, h = tid&3) owns E[r][h*32..+31] in regs.
// x lives in smem with 36-word group padding -> conflict-free LDS.128.
// ---------------------------------------------------------------------------
__device__ __forceinline__ float matvec_quarter(const float* __restrict__ E,
                                                const float* __restrict__ xbase,
                                                int h)
{
    const float4* x4 = (const float4*)xbase + h * 9;   // 36 words = 9 float4
    float a0 = 0.f, a1 = 0.f, a2 = 0.f, a3 = 0.f;
#pragma unroll
    for (int k = 0; k < 8; k++) {
        const float4 xv = x4[k];
        a0 = fmaf(E[4 * k + 0], xv.x, a0);
        a1 = fmaf(E[4 * k + 1], xv.y, a1);
        a2 = fmaf(E[4 * k + 2], xv.z, a2);
        a3 = fmaf(E[4 * k + 3], xv.w, a3);
    }
    float sum = (a0 + a1) + (a2 + a3);
    sum += __shfl_xor_sync(0xffffffffu, sum, 1);
    sum += __shfl_xor_sync(0xffffffffu, sum, 2);
    return sum;
}

__global__ void __launch_bounds__(512) solve_kernel(
    const float* __restrict__ pi,
    const float* __restrict__ sigma,
    float* __restrict__ out)
{
    __shared__ __align__(16) float sm_d[144];
    __shared__ __align__(16) float sm_u[144];
    __shared__ __align__(16) float xA[144];
    __shared__ __align__(16) float xB[144];
    __shared__ __align__(16) float sm_a[NQ];

    const int tid = threadIdx.x;
    const int b = blockIdx.x;
    const int r = tid >> 2;
    const int h = tid & 3;

    if (tid < NQ) {
        const float q  = g_q[b * NQ + tid];
        const float p  = g_p[b * NQ + tid];
        const float om = g_o[b * NQ + tid];
        const float d  = p * p / om + 1e-6f;
        sm_d[PX(tid)] = d;
        sm_u[PX(tid)] = (p * q / om) / d;
        sm_a[tid] = pi[b * NQ + tid];
    }
    __syncthreads();

    // Build E = (TAU*sigma + 1e-6 I) * diag(d) into registers (32 per thread).
    float E[32];
    const float4* sg = (const float4*)(sigma + (size_t)b * NQ * NQ) + r * 32 + h * 8;
    const float4* d4 = (const float4*)sm_d + h * 9;
#pragma unroll
    for (int k = 0; k < 8; k++) {
        const float4 s = sg[k];
        const float4 dv = d4[k];
        const int j = h * 32 + 4 * k;
        E[4 * k + 0] = (TAUC * s.x + ((r == j + 0) ? 1e-6f : 0.f)) * dv.x;
        E[4 * k + 1] = (TAUC * s.y + ((r == j + 1) ? 1e-6f : 0.f)) * dv.y;
        E[4 * k + 2] = (TAUC * s.z + ((r == j + 2) ? 1e-6f : 0.f)) * dv.z;
        E[4 * k + 3] = (TAUC * s.w + ((r == j + 3) ? 1e-6f : 0.f)) * dv.w;
    }

    // a = pi + M t = pi + E * (t./d);  x0 = a
    {
        const float s = matvec_quarter(E, sm_u, h);
        if (h == 0) {
            const float a = sm_a[r] + s;
            sm_a[r] = a;
            xA[PX(r)] = a;
        }
    }
    __syncthreads();

    // Richardson: x <- a - E x   (converges to (I + E)^{-1} a)
#pragma unroll 1
    for (int it = 0; it < NITER / 2; it++) {
        float s = matvec_quarter(E, xA, h);
        if (h == 0) xB[PX(r)] = sm_a[r] - s;
        __syncthreads();
        s = matvec_quarter(E, xB, h);
        if (h == 0) xA[PX(r)] = sm_a[r] - s;
        __syncthreads();
    }

    if (tid < NQ) out[b * NQ + tid] = xA[PX(tid)];
}

// ---------------------------------------------------------------------------
extern "C" void kernel_launch(void* const* d_in, const int* in_sizes, int n_in,
                              void* d_out, int out_size)
{
    const float* hidden = (const float*)d_in[0];
    const float* pi     = (const float*)d_in[1];
    const float* sigma  = (const float*)d_in[2];
    const float* Wq     = (const float*)d_in[3];
    const float* bq     = (const float*)d_in[4];
    const float* Wp     = (const float*)d_in[5];
    const float* bp     = (const float*)d_in[6];
    const float* Wo     = (const float*)d_in[7];
    const float* bo     = (const float*)d_in[8];

    dim3 gridA(BQ / BT, 3, 1);
    gemm_act_kernel<<<gridA, 256>>>(hidden, Wq, Wp, Wo, bq, bp, bo);
    solve_kernel<<<BQ, 512>>>(pi, sigma, (float*)d_out);
}

// round 12
// speedup vs baseline: 2.9954x; 1.1904x over previous
#include <cuda_runtime.h>
#include <math.h>

#define BQ 2048
#define NQ 128
#define HQ 512
#define TAUC 0.05f
#define BT 8
#define KC 32
#define NITER 4    // Richardson iterations (even); 7 apps = fp32 floor, rho<=0.17

// padded index: 32-float groups padded to 36 words -> banks (4g + i) % 32
#define PX(i) ((((i) >> 5) * 36) + ((i) & 31))

// scratch (allocation-free rule: __device__ globals)
__device__ float g_q[BQ * NQ];
__device__ float g_p[BQ * NQ];
__device__ float g_o[BQ * NQ];

// ---------------------------------------------------------------------------
// Kernel A: tiled GEMM. CTA = 8 batches x 128 n, one weight (blockIdx.y).
// W staged through smem with REGISTER PREFETCH double-buffering:
// chunk c+1 LDG issued before computing chunk c -> LDG latency hidden.
// ---------------------------------------------------------------------------
__global__ void __launch_bounds__(256) gemm_act_kernel(
    const float* __restrict__ hidden,
    const float* __restrict__ Wq, const float* __restrict__ Wp,
    const float* __restrict__ Wo,
    const float* __restrict__ bq, const float* __restrict__ bp,
    const float* __restrict__ bo)
{
    __shared__ float Ht[BT][HQ];        // 16 KB
    __shared__ float Wt[NQ][KC + 1];    // 16.5 KB, pad 33 -> bank (n+kk)%32

    const int tid = threadIdx.x;
    const int b0 = blockIdx.x * BT;
    const int w  = blockIdx.y;

    const float* W    = (w == 0) ? Wq : (w == 1) ? Wp : Wo;
    const float* bias = (w == 0) ? bq : (w == 1) ? bp : bo;
    float* gout       = (w == 0) ? g_q : (w == 1) ? g_p : g_o;

    // load hidden tile (coalesced float4)
    {
        const float4* hg = (const float4*)(hidden + (size_t)b0 * HQ);
        float4* hs = (float4*)&Ht[0][0];
#pragma unroll
        for (int i = 0; i < (BT * HQ / 4) / 256; i++)
            hs[tid + 256 * i] = hg[tid + 256 * i];
    }

    const int n    = tid & 127;
    const int kh   = tid >> 7;
    const int wrp  = tid >> 5;
    const int lane = tid & 31;
    const int rowsub = lane >> 3;      // 4 rows per warp per instr
    const int f4     = lane & 7;       // 8 float4 per 128B row
    const float4* W4 = (const float4*)W;

    // staging rows for this thread (4 rows, one float4 each per chunk)
    int srow[4];
#pragma unroll
    for (int i = 0; i < 4; i++) srow[i] = wrp * 16 + i * 4 + rowsub;

    float4 v[4];
    // prefetch chunk 0
#pragma unroll
    for (int i = 0; i < 4; i++)
        v[i] = W4[(size_t)srow[i] * (HQ / 4) + f4];

    float acc[8] = {0.f, 0.f, 0.f, 0.f, 0.f, 0.f, 0.f, 0.f};

#pragma unroll 1
    for (int c = 0; c < HQ / KC; c++) {
        // store prefetched chunk c into Wt
        __syncthreads();
#pragma unroll
        for (int i = 0; i < 4; i++) {
            Wt[srow[i]][f4 * 4 + 0] = v[i].x;
            Wt[srow[i]][f4 * 4 + 1] = v[i].y;
            Wt[srow[i]][f4 * 4 + 2] = v[i].z;
            Wt[srow[i]][f4 * 4 + 3] = v[i].w;
        }
        __syncthreads();

        // prefetch chunk c+1 (LDG in flight during compute below)
        if (c + 1 < HQ / KC) {
#pragma unroll
            for (int i = 0; i < 4; i++)
                v[i] = W4[(size_t)srow[i] * (HQ / 4) + (c + 1) * (KC / 4) + f4];
        }

        const int k0 = c * KC;
#pragma unroll
        for (int j = 0; j < 4; j++) {
            const int kk = kh * 16 + j * 4;
            const float w0 = Wt[n][kk + 0];
            const float w1 = Wt[n][kk + 1];
            const float w2 = Wt[n][kk + 2];
            const float w3 = Wt[n][kk + 3];
#pragma unroll
            for (int m = 0; m < 8; m++) {
                const float4 hv = *(const float4*)&Ht[m][k0 + kk];
                acc[m] = fmaf(hv.x, w0, fmaf(hv.y, w1,
                         fmaf(hv.z, w2, fmaf(hv.w, w3, acc[m]))));
            }
        }
    }

    // combine the two k-halves via smem (reuse Wt as scratch: 1024 floats)
    __syncthreads();
    float* red = &Wt[0][0];
    if (kh == 1) {
#pragma unroll
        for (int m = 0; m < 8; m++) red[n * 8 + m] = acc[m];
    }
    __syncthreads();
    if (kh == 0) {
        const float bv = bias[n];
#pragma unroll
        for (int m = 0; m < 8; m++) {
            const float l = acc[m] + red[n * 8 + m] + bv;
            float v;
            if (w == 0) {
                v = tanhf(l);                                         // q
            } else if (w == 1) {
                v = 1.0f / (1.0f + expf(-l));                         // p
            } else {
                v = fmaxf(l, 0.0f) + log1pf(expf(-fabsf(l))) + 1e-6f; // omega
            }
            gout[(size_t)(b0 + m) * NQ + n] = v;
        }
    }
}

// ---------------------------------------------------------------------------
// Kernel B: per-batch solve of (I + M D) mu = pi + M t via Richardson.
// 512 threads: thread (r = tid>>2, h = tid&3) owns E[r][h*32..+31] in regs.
// x in smem with 36-word group padding -> conflict-free LDS.128.
// launch_bounds(512,2): cap at 64 regs so 2 CTAs/SM (occ ~50%).
// ---------------------------------------------------------------------------
__device__ __forceinline__ float matvec_quarter(const float* __restrict__ E,
                                                const float* __restrict__ xbase,
                                                int h)
{
    const float4* x4 = (const float4*)xbase + h * 9;   // 36 words = 9 float4
    float a0 = 0.f, a1 = 0.f, a2 = 0.f, a3 = 0.f;
#pragma unroll
    for (int k = 0; k < 8; k++) {
        const float4 xv = x4[k];
        a0 = fmaf(E[4 * k + 0], xv.x, a0);
        a1 = fmaf(E[4 * k + 1], xv.y, a1);
        a2 = fmaf(E[4 * k + 2], xv.z, a2);
        a3 = fmaf(E[4 * k + 3], xv.w, a3);
    }
    float sum = (a0 + a1) + (a2 + a3);
    sum += __shfl_xor_sync(0xffffffffu, sum, 1);
    sum += __shfl_xor_sync(0xffffffffu, sum, 2);
    return sum;
}

__global__ void __launch_bounds__(512, 2) solve_kernel(
    const float* __restrict__ pi,
    const float* __restrict__ sigma,
    float* __restrict__ out)
{
    __shared__ __align__(16) float sm_d[144];
    __shared__ __align__(16) float sm_u[144];
    __shared__ __align__(16) float xA[144];
    __shared__ __align__(16) float xB[144];
    __shared__ __align__(16) float sm_a[NQ];

    const int tid = threadIdx.x;
    const int b = blockIdx.x;
    const int r = tid >> 2;
    const int h = tid & 3;

    if (tid < NQ) {
        const float q  = g_q[b * NQ + tid];
        const float p  = g_p[b * NQ + tid];
        const float om = g_o[b * NQ + tid];
        const float d  = p * p / om + 1e-6f;
        sm_d[PX(tid)] = d;
        sm_u[PX(tid)] = (p * q / om) / d;
        sm_a[tid] = pi[b * NQ + tid];
    }
    __syncthreads();

    // Build E = (TAU*sigma + 1e-6 I) * diag(d) into registers (32 per thread).
    float E[32];
    const float4* sg = (const float4*)(sigma + (size_t)b * NQ * NQ) + r * 32 + h * 8;
    const float4* d4 = (const float4*)sm_d + h * 9;
#pragma unroll
    for (int k = 0; k < 8; k++) {
        const float4 s = sg[k];
        const float4 dv = d4[k];
        const int j = h * 32 + 4 * k;
        E[4 * k + 0] = (TAUC * s.x + ((r == j + 0) ? 1e-6f : 0.f)) * dv.x;
        E[4 * k + 1] = (TAUC * s.y + ((r == j + 1) ? 1e-6f : 0.f)) * dv.y;
        E[4 * k + 2] = (TAUC * s.z + ((r == j + 2) ? 1e-6f : 0.f)) * dv.z;
        E[4 * k + 3] = (TAUC * s.w + ((r == j + 3) ? 1e-6f : 0.f)) * dv.w;
    }

    // a = pi + M t = pi + E * (t./d);  x0 = a
    {
        const float s = matvec_quarter(E, sm_u, h);
        if (h == 0) {
            const float a = sm_a[r] + s;
            sm_a[r] = a;
            xA[PX(r)] = a;
        }
    }
    __syncthreads();

    // Richardson: x <- a - E x   (converges to (I + E)^{-1} a)
#pragma unroll 1
    for (int it = 0; it < NITER / 2; it++) {
        float s = matvec_quarter(E, xA, h);
        if (h == 0) xB[PX(r)] = sm_a[r] - s;
        __syncthreads();
        s = matvec_quarter(E, xB, h);
        if (h == 0) xA[PX(r)] = sm_a[r] - s;
        __syncthreads();
    }

    if (tid < NQ) out[b * NQ + tid] = xA[PX(tid)];
}

// ---------------------------------------------------------------------------
extern "C" void kernel_launch(void* const* d_in, const int* in_sizes, int n_in,
                              void* d_out, int out_size)
{
    const float* hidden = (const float*)d_in[0];
    const float* pi     = (const float*)d_in[1];
    const float* sigma  = (const float*)d_in[2];
    const float* Wq     = (const float*)d_in[3];
    const float* bq     = (const float*)d_in[4];
    const float* Wp     = (const float*)d_in[5];
    const float* bp     = (const float*)d_in[6];
    const float* Wo     = (const float*)d_in[7];
    const float* bo     = (const float*)d_in[8];

    dim3 gridA(BQ / BT, 3, 1);
    gemm_act_kernel<<<gridA, 256>>>(hidden, Wq, Wp, Wo, bq, bp, bo);
    solve_kernel<<<BQ, 512>>>(pi, sigma, (float*)d_out);
}